// round 1
// baseline (speedup 1.0000x reference)
#include <cuda_runtime.h>
#include <math.h>

#define T_STEPS 5
#define HID 64
#define LH 128
#define G4 (4*LH)   // 512

#define MAX_N 16000
#define MAX_M (T_STEPS*MAX_N)   // 80000

// ---------------- scratch (device globals; no runtime allocation) ----------------
__device__ float d_deg [MAX_N];
__device__ float d_dinv[MAX_N];
__device__ float d_acc [MAX_N*T_STEPS];
__device__ float d_G  [(size_t)MAX_M*G4];   // 160 MB: ih-precompute buffer (reused layer0/layer1)
__device__ float d_y0 [(size_t)MAX_M*LH];   // 40 MB: layer-0 hidden sequence (doubles as h chain)
__device__ float d_hA [(size_t)MAX_N*LH];
__device__ float d_hB [(size_t)MAX_N*LH];
__device__ float d_c  [(size_t)MAX_N*LH];

__device__ __forceinline__ float sigm(float x) { return 1.0f/(1.0f + __expf(-x)); }

// ---------------- GCN scalar pipeline ----------------
__global__ void k_deg_init(float* deg, int n) {
    int i = blockIdx.x*blockDim.x + threadIdx.x;
    if (i < n) deg[i] = 1.0f;                       // self-loop
}

__global__ void k_deg_edges(const int* __restrict__ dst, float* deg, int E) {
    int e = blockIdx.x*blockDim.x + threadIdx.x;
    if (e < E) atomicAdd(&deg[dst[e]], 1.0f);
}

__global__ void k_dinv_accinit(const float* __restrict__ x, const float* __restrict__ deg,
                               float* __restrict__ dinv, float* __restrict__ acc, int n) {
    int i = blockIdx.x*blockDim.x + threadIdx.x;
    if (i >= n) return;
    float di = rsqrtf(deg[i]);
    dinv[i] = di;
#pragma unroll
    for (int t = 0; t < T_STEPS; t++)
        acc[i*T_STEPS + t] = x[i*T_STEPS + t] * di;  // self-loop term (pre final dinv[d] scale)
}

__global__ void k_scatter(const int* __restrict__ src, const int* __restrict__ dst,
                          const float* __restrict__ x, const float* __restrict__ dinv,
                          float* __restrict__ acc, int E) {
    int e = blockIdx.x*blockDim.x + threadIdx.x;
    if (e >= E) return;
    int s = src[e], d = dst[e];
    float ds = dinv[s];
#pragma unroll
    for (int t = 0; t < T_STEPS; t++)
        atomicAdd(&acc[d*T_STEPS + t], x[s*T_STEPS + t] * ds);
}

// ---------------- P0: G[m,j] = relu(agg_m*gw+gb) @ Wih0^T + bih0+bhh0  (M=80000,N=512,K=64) ----------------
__global__ void k_p0(const float* __restrict__ acc, const float* __restrict__ dinv,
                     const float* __restrict__ gw, const float* __restrict__ gb,
                     const float* __restrict__ Wih,        // (512,64)
                     const float* __restrict__ bih, const float* __restrict__ bhh,
                     float* __restrict__ G, int NN, int M) {
    __shared__ float As[32][129];
    __shared__ float Ws[32][129];
    __shared__ float rowa[128];
    const int m0 = blockIdx.x*128, n0 = blockIdx.y*128;
    const int tid = threadIdx.x, ty = tid >> 4, tx = tid & 15;

    if (tid < 128) {
        int m = m0 + tid;
        float v = 0.f;
        if (m < M) { int t = m / NN, n = m - t*NN; v = acc[n*T_STEPS + t] * dinv[n]; }
        rowa[tid] = v;
    }
    __syncthreads();

    float accv[8][8];
#pragma unroll
    for (int r = 0; r < 8; r++)
#pragma unroll
        for (int c = 0; c < 8; c++) accv[r][c] = 0.f;

#pragma unroll
    for (int kc = 0; kc < 2; kc++) {
        const int k0 = kc*32;
#pragma unroll
        for (int it = 0; it < 16; it++) {              // feat tile (computed, not loaded)
            int idx = tid + it*256;
            int k = idx & 31, m = idx >> 5;
            As[k][m] = fmaxf(rowa[m]*gw[k0+k] + gb[k0+k], 0.f);
        }
#pragma unroll
        for (int it = 0; it < 16; it++) {              // weight tile (transposed)
            int idx = tid + it*256;
            int k = idx & 31, j = idx >> 5;
            Ws[k][j] = Wih[(n0+j)*HID + k0 + k];
        }
        __syncthreads();
#pragma unroll
        for (int k = 0; k < 32; k++) {
            float a[8], b[8];
#pragma unroll
            for (int r = 0; r < 8; r++) a[r] = As[k][ty + 16*r];
#pragma unroll
            for (int c = 0; c < 8; c++) b[c] = Ws[k][tx + 16*c];
#pragma unroll
            for (int r = 0; r < 8; r++)
#pragma unroll
                for (int c = 0; c < 8; c++) accv[r][c] = fmaf(a[r], b[c], accv[r][c]);
        }
        __syncthreads();
    }
#pragma unroll
    for (int r = 0; r < 8; r++) {
        int m = m0 + ty + 16*r;
        if (m >= M) continue;
#pragma unroll
        for (int c = 0; c < 8; c++) {
            int j = n0 + tx + 16*c;
            G[(size_t)m*G4 + j] = accv[r][c] + bih[j] + bhh[j];
        }
    }
}

// ---------------- P1: G = A(M,128) @ W(512,128)^T + b1+b2 ----------------
__global__ void k_gemm_bias(const float* __restrict__ A, const float* __restrict__ W,
                            const float* __restrict__ b1, const float* __restrict__ b2,
                            float* __restrict__ G, int M) {
    __shared__ float As[32][129];
    __shared__ float Ws[32][129];
    const int m0 = blockIdx.x*128, n0 = blockIdx.y*128;
    const int tid = threadIdx.x, ty = tid >> 4, tx = tid & 15;

    float accv[8][8];
#pragma unroll
    for (int r = 0; r < 8; r++)
#pragma unroll
        for (int c = 0; c < 8; c++) accv[r][c] = 0.f;

#pragma unroll
    for (int kc = 0; kc < 4; kc++) {
        const int k0 = kc*32;
#pragma unroll
        for (int it = 0; it < 16; it++) {
            int idx = tid + it*256;
            int k = idx & 31, m = idx >> 5;
            int gm = m0 + m;
            As[k][m] = (gm < M) ? A[(size_t)gm*LH + k0 + k] : 0.f;
        }
#pragma unroll
        for (int it = 0; it < 16; it++) {
            int idx = tid + it*256;
            int k = idx & 31, j = idx >> 5;
            Ws[k][j] = W[(n0+j)*LH + k0 + k];
        }
        __syncthreads();
#pragma unroll
        for (int k = 0; k < 32; k++) {
            float a[8], b[8];
#pragma unroll
            for (int r = 0; r < 8; r++) a[r] = As[k][ty + 16*r];
#pragma unroll
            for (int c = 0; c < 8; c++) b[c] = Ws[k][tx + 16*c];
#pragma unroll
            for (int r = 0; r < 8; r++)
#pragma unroll
                for (int c = 0; c < 8; c++) accv[r][c] = fmaf(a[r], b[c], accv[r][c]);
        }
        __syncthreads();
    }
#pragma unroll
    for (int r = 0; r < 8; r++) {
        int m = m0 + ty + 16*r;
        if (m >= M) continue;
#pragma unroll
        for (int c = 0; c < 8; c++) {
            int j = n0 + tx + 16*c;
            G[(size_t)m*G4 + j] = accv[r][c] + b1[j] + b2[j];
        }
    }
}

// ---------------- step 0 (h=0, c=0): pure elementwise gates ----------------
__global__ void k_gates0(const float* __restrict__ G, float* __restrict__ h,
                         float* __restrict__ c, int M) {
    int idx = blockIdx.x*blockDim.x + threadIdx.x;
    if (idx >= M*LH) return;
    int m = idx >> 7, u = idx & 127;
    const float* g = G + (size_t)m*G4;
    float gi = sigm(g[u]);
    float gg = tanhf(g[2*LH + u]);
    float go = sigm(g[3*LH + u]);
    float cn = gi*gg;                 // f-gate * 0 drops out
    c[idx] = cn;
    h[idx] = go * tanhf(cn);
}

// ---------------- fused recurrent step: g = P + h@Whh^T, gate math, c/h update ----------------
// Block: 128 rows x (4 gates x 32 units). Column-permuted GEMM so all 4 gates of a
// unit live in one thread's registers -> no gate buffer.
__global__ void k_step(const float* __restrict__ h_in, float* __restrict__ c,
                       const float* __restrict__ P, const float* __restrict__ Whh,   // (512,128)
                       float* __restrict__ h_out, int M) {
    __shared__ float As[32][129];
    __shared__ float Ws[32][129];
    const int m0 = blockIdx.x*128;
    const int u0 = blockIdx.y*32;
    const int tid = threadIdx.x, ty = tid >> 4, tx = tid & 15;

    float accv[8][8];
#pragma unroll
    for (int r = 0; r < 8; r++)
#pragma unroll
        for (int cc = 0; cc < 8; cc++) accv[r][cc] = 0.f;

#pragma unroll
    for (int kc = 0; kc < 4; kc++) {
        const int k0 = kc*32;
#pragma unroll
        for (int it = 0; it < 16; it++) {
            int idx = tid + it*256;
            int k = idx & 31, m = idx >> 5;
            int gm = m0 + m;
            As[k][m] = (gm < M) ? h_in[(size_t)gm*LH + k0 + k] : 0.f;
        }
#pragma unroll
        for (int it = 0; it < 16; it++) {
            int idx = tid + it*256;
            int k = idx & 31, jl = idx >> 5;           // jl in [0,128): gate=jl/32, uu=jl%32
            int gte = jl >> 5, uu = jl & 31;
            Ws[k][jl] = Whh[(gte*LH + u0 + uu)*LH + k0 + k];
        }
        __syncthreads();
#pragma unroll
        for (int k = 0; k < 32; k++) {
            float a[8], b[8];
#pragma unroll
            for (int r = 0; r < 8; r++) a[r] = As[k][ty + 16*r];
#pragma unroll
            for (int cc = 0; cc < 8; cc++) b[cc] = Ws[k][tx + 16*cc];
#pragma unroll
            for (int r = 0; r < 8; r++)
#pragma unroll
                for (int cc = 0; cc < 8; cc++) accv[r][cc] = fmaf(a[r], b[cc], accv[r][cc]);
        }
        __syncthreads();
    }
    // epilogue: col cc maps to local column tx+16*cc = 32*g + (tx+16*q), cc = 2g+q
#pragma unroll
    for (int r = 0; r < 8; r++) {
        int m = m0 + ty + 16*r;
        if (m >= M) continue;
        const float* Pm = P + (size_t)m*G4;
#pragma unroll
        for (int q = 0; q < 2; q++) {
            int u = u0 + tx + 16*q;
            float gi = accv[r][0+q] + Pm[u];
            float gf = accv[r][2+q] + Pm[LH   + u];
            float gg = accv[r][4+q] + Pm[2*LH + u];
            float go = accv[r][6+q] + Pm[3*LH + u];
            float co = c[(size_t)m*LH + u];
            float cn = sigm(gf)*co + sigm(gi)*tanhf(gg);
            float hn = sigm(go)*tanhf(cn);
            c[(size_t)m*LH + u]    = cn;
            h_out[(size_t)m*LH + u] = hn;
        }
    }
}

// ---------------- head: out = x_t + relu(h@pw1^T+pb1)@pw2^T + pb2 ----------------
__global__ void k_head(const float* __restrict__ h, const float* __restrict__ x,
                       const float* __restrict__ pw1, const float* __restrict__ pb1,
                       const float* __restrict__ pw2, const float* __restrict__ pb2,
                       float* __restrict__ out, int NN) {
    __shared__ float w1s[128][65];     // transposed [k][j]
    __shared__ float w2s[64], b1s[64];
    const int tid = threadIdx.x;
    for (int idx = tid; idx < 64*128; idx += 256) {
        int j = idx >> 7, k = idx & 127;
        w1s[k][j] = pw1[idx];
    }
    if (tid < 64) { w2s[tid] = pw2[tid]; b1s[tid] = pb1[tid]; }
    __syncthreads();

    int warp = tid >> 5, lane = tid & 31;
    int n = blockIdx.x*8 + warp;
    if (n >= NN) return;
    const float* hr = h + (size_t)n*LH;
    float s0 = b1s[lane], s1 = b1s[lane+32];
#pragma unroll 8
    for (int k = 0; k < 128; k++) {
        float hv = hr[k];
        s0 = fmaf(hv, w1s[k][lane],      s0);
        s1 = fmaf(hv, w1s[k][lane+32],   s1);
    }
    float part = fmaxf(s0, 0.f)*w2s[lane] + fmaxf(s1, 0.f)*w2s[lane+32];
#pragma unroll
    for (int o = 16; o; o >>= 1) part += __shfl_xor_sync(0xffffffffu, part, o);
    if (lane == 0) out[n] = part + pb2[0] + x[n*T_STEPS + (T_STEPS-1)];
}

// ---------------- launcher ----------------
extern "C" void kernel_launch(void* const* d_in, const int* in_sizes, int n_in,
                              void* d_out, int out_size) {
    const float* x    = (const float*)d_in[0];
    const int*   ei   = (const int*)  d_in[1];
    const float* gw   = (const float*)d_in[2];
    const float* gb   = (const float*)d_in[3];
    const float* wih0 = (const float*)d_in[4];
    const float* whh0 = (const float*)d_in[5];
    const float* bih0 = (const float*)d_in[6];
    const float* bhh0 = (const float*)d_in[7];
    const float* wih1 = (const float*)d_in[8];
    const float* whh1 = (const float*)d_in[9];
    const float* bih1 = (const float*)d_in[10];
    const float* bhh1 = (const float*)d_in[11];
    const float* pw1  = (const float*)d_in[12];
    const float* pb1  = (const float*)d_in[13];
    const float* pw2  = (const float*)d_in[14];
    const float* pb2  = (const float*)d_in[15];
    float* out = (float*)d_out;

    const int NN = in_sizes[0] / T_STEPS;   // 16000
    const int E  = in_sizes[1] / 2;         // 256000
    const int M  = T_STEPS * NN;            // 80000
    const int* src = ei;
    const int* dst = ei + E;

    float *p_deg, *p_dinv, *p_acc, *p_G, *p_y0, *p_hA, *p_hB, *p_c;
    cudaGetSymbolAddress((void**)&p_deg,  d_deg);
    cudaGetSymbolAddress((void**)&p_dinv, d_dinv);
    cudaGetSymbolAddress((void**)&p_acc,  d_acc);
    cudaGetSymbolAddress((void**)&p_G,    d_G);
    cudaGetSymbolAddress((void**)&p_y0,   d_y0);
    cudaGetSymbolAddress((void**)&p_hA,   d_hA);
    cudaGetSymbolAddress((void**)&p_hB,   d_hB);
    cudaGetSymbolAddress((void**)&p_c,    d_c);

    // GCN scalar aggregation
    k_deg_init   <<<(NN + 255)/256, 256>>>(p_deg, NN);
    k_deg_edges  <<<(E  + 255)/256, 256>>>(dst, p_deg, E);
    k_dinv_accinit<<<(NN + 255)/256, 256>>>(x, p_deg, p_dinv, p_acc, NN);
    k_scatter    <<<(E  + 255)/256, 256>>>(src, dst, x, p_dinv, p_acc, E);

    // Layer-0 ih precompute for all t (one big parallel GEMM with fused GCN feature build)
    dim3 gP((M + 127)/128, 4);
    k_p0<<<gP, 256>>>(p_acc, p_dinv, gw, gb, wih0, bih0, bhh0, p_G, NN, M);

    // Layer 0: t=0 elementwise, t=1..4 fused GEMM+gates (y0 buffer is the h chain)
    dim3 gS((NN + 127)/128, 4);
    k_gates0<<<(NN*LH + 255)/256, 256>>>(p_G, p_y0, p_c, NN);
    for (int t = 1; t < T_STEPS; t++)
        k_step<<<gS, 256>>>(p_y0 + (size_t)(t-1)*NN*LH, p_c,
                            p_G + (size_t)t*NN*G4, whh0,
                            p_y0 + (size_t)t*NN*LH, NN);

    // Layer-1 ih precompute over full y0 sequence
    k_gemm_bias<<<gP, 256>>>(p_y0, wih1, bih1, bhh1, p_G, M);

    // Layer 1
    k_gates0<<<(NN*LH + 255)/256, 256>>>(p_G, p_hA, p_c, NN);
    float* hin = p_hA; float* hout = p_hB;
    for (int t = 1; t < T_STEPS; t++) {
        k_step<<<gS, 256>>>(hin, p_c, p_G + (size_t)t*NN*G4, whh1, hout, NN);
        float* tmp = hin; hin = hout; hout = tmp;
    }

    // Head + residual
    k_head<<<(NN + 7)/8, 256>>>(hin, x, pw1, pb1, pw2, pb2, out, NN);
}

// round 2
// speedup vs baseline: 2.2444x; 2.2444x over previous
#include <cuda_runtime.h>
#include <math.h>

#define T_STEPS 5
#define HID 64
#define LH 128

#define MAX_N 16000
#define MAX_M (T_STEPS*MAX_N)

// ---------------- scratch (device globals; no runtime allocation) ----------------
__device__ float d_deg [MAX_N];
__device__ float d_dinv[MAX_N];
__device__ float d_acc [MAX_N*T_STEPS];
__device__ float d_a   [MAX_M];                 // GCN scalar per (t,node), laid out [t][n]
__device__ float d_y0  [(size_t)MAX_M*LH];      // layer-0 hidden sequence
__device__ float d_hA  [(size_t)MAX_N*LH];
__device__ float d_hB  [(size_t)MAX_N*LH];
__device__ float d_c   [(size_t)MAX_N*LH];

__device__ __forceinline__ float sigm_(float x)  { return __fdividef(1.0f, 1.0f + __expf(-x)); }
__device__ __forceinline__ float tanh_(float x)  { return __fdividef(2.0f, 1.0f + __expf(-2.0f*x)) - 1.0f; }

// ---------------- GCN scalar pipeline ----------------
__global__ void k_deg_init(float* deg, int n) {
    int i = blockIdx.x*blockDim.x + threadIdx.x;
    if (i < n) deg[i] = 1.0f;                       // self-loop
}

__global__ void k_deg_edges(const int* __restrict__ dst, float* deg, int E) {
    int e = blockIdx.x*blockDim.x + threadIdx.x;
    if (e < E) atomicAdd(&deg[dst[e]], 1.0f);
}

__global__ void k_dinv_accinit(const float* __restrict__ x, const float* __restrict__ deg,
                               float* __restrict__ dinv, float* __restrict__ acc, int n) {
    int i = blockIdx.x*blockDim.x + threadIdx.x;
    if (i >= n) return;
    float di = rsqrtf(deg[i]);
    dinv[i] = di;
#pragma unroll
    for (int t = 0; t < T_STEPS; t++)
        acc[i*T_STEPS + t] = x[i*T_STEPS + t] * di;  // self-loop term
}

__global__ void k_scatter(const int* __restrict__ src, const int* __restrict__ dst,
                          const float* __restrict__ x, const float* __restrict__ dinv,
                          float* __restrict__ acc, int E) {
    int e = blockIdx.x*blockDim.x + threadIdx.x;
    if (e >= E) return;
    int s = src[e], d = dst[e];
    float ds = dinv[s];
#pragma unroll
    for (int t = 0; t < T_STEPS; t++)
        atomicAdd(&acc[d*T_STEPS + t], x[s*T_STEPS + t] * ds);
}

__global__ void k_afin(const float* __restrict__ acc, const float* __restrict__ dinv,
                       float* __restrict__ a, int NN) {
    int i = blockIdx.x*blockDim.x + threadIdx.x;
    if (i >= NN*T_STEPS) return;
    int n = i % NN, t = i / NN;
    a[i] = acc[n*T_STEPS + t] * dinv[n];
}

// ---------------- unified fused LSTM-step GEMM ----------------
// Computes g = A1 @ W1^T (+ H @ W2^T) + b1 + b2 with the 4x128 gate columns
// permuted so one block owns all 4 gates for a 32-unit slice, then does the
// LSTM gate math + c/h update in-register. No gate buffer ever hits HBM.
//
// FEAT: A1 is the rank-1 GCN scalar a[m]; features relu(a*gw+gb) are built
//       in-register (K1 = 64). Otherwise A1 is a dense (M,128) activation.
// HAS_H: adds the recurrent H @ W2^T contribution (K2 = 128) and reads c.
template<int NC1, bool FEAT, bool HAS_H>
__global__ void __launch_bounds__(256, 2)
k_fused(const float* __restrict__ A1,
        const float* __restrict__ gw, const float* __restrict__ gb,
        const float* __restrict__ W1,        // (512, K1) row-major
        const float* __restrict__ Hh,        // (M, 128) or unused
        const float* __restrict__ W2,        // (512, 128) or unused
        const float* __restrict__ b1, const float* __restrict__ b2,
        float* __restrict__ c, float* __restrict__ h_out, int M)
{
    constexpr int K1 = NC1*32;
    constexpr int NC = NC1 + (HAS_H ? 4 : 0);
    __shared__ float As[32][129];
    __shared__ float Ws[32][129];
    __shared__ float rowa[128];

    const int m0  = blockIdx.x*128;
    const int u0  = blockIdx.y*32;
    const int tid = threadIdx.x;
    const int ty  = tid >> 4, tx = tid & 15;
    const int k4  = tid & 7;           // float4 slot within a 32-float k-row
    const int r0  = tid >> 3;          // base row 0..31 (rows r0 + 32*i)

    if (FEAT) {
        if (tid < 128) {
            int m = m0 + tid;
            rowa[tid] = (m < M) ? A1[m] : 0.f;
        }
    }

    int jrow[4];                       // global weight-row per local column
#pragma unroll
    for (int i = 0; i < 4; i++) {
        int jl = r0 + 32*i;                       // local col 0..127
        jrow[i] = ((jl >> 5) * LH) + u0 + (jl & 31);   // gate*128 + unit
    }

    float4 pa[4], pw[4];

    auto ldW = [&](int ch) {
        const float* W; int Ks, k0;
        if (ch < NC1) { W = W1; Ks = K1; k0 = ch*32; }
        else          { W = W2; Ks = LH; k0 = (ch - NC1)*32; }
#pragma unroll
        for (int i = 0; i < 4; i++)
            pw[i] = *(const float4*)(W + (size_t)jrow[i]*Ks + k0 + 4*k4);
    };
    auto ldA = [&](int ch) {
        if (FEAT && ch < NC1) return;             // built from rowa at STS time
        const float* A; int k0;
        if (ch < NC1) { A = A1; k0 = ch*32; }     // dense (M,128) input
        else          { A = Hh; k0 = (ch - NC1)*32; }
#pragma unroll
        for (int i = 0; i < 4; i++) {
            int m = m0 + r0 + 32*i;
            pa[i] = (m < M) ? *(const float4*)(A + (size_t)m*LH + k0 + 4*k4)
                            : make_float4(0.f, 0.f, 0.f, 0.f);
        }
    };

    float accv[8][8];
#pragma unroll
    for (int r = 0; r < 8; r++)
#pragma unroll
        for (int cc = 0; cc < 8; cc++) accv[r][cc] = 0.f;

    ldW(0); ldA(0);

    for (int ch = 0; ch < NC; ch++) {
        __syncthreads();               // previous chunk's compute done (and rowa ready on ch=0)
        // ---- scatter staged regs into smem (conflict-free: bank = 4*k4+s+row) ----
#pragma unroll
        for (int i = 0; i < 4; i++) {
            int jl = r0 + 32*i;
            Ws[4*k4+0][jl] = pw[i].x;
            Ws[4*k4+1][jl] = pw[i].y;
            Ws[4*k4+2][jl] = pw[i].z;
            Ws[4*k4+3][jl] = pw[i].w;
        }
        if (FEAT && ch < NC1) {
            int k0 = ch*32;
            float g0 = gw[k0+4*k4+0], g1 = gw[k0+4*k4+1], g2 = gw[k0+4*k4+2], g3 = gw[k0+4*k4+3];
            float c0 = gb[k0+4*k4+0], c1 = gb[k0+4*k4+1], c2 = gb[k0+4*k4+2], c3 = gb[k0+4*k4+3];
#pragma unroll
            for (int i = 0; i < 4; i++) {
                int m = r0 + 32*i;
                float av = rowa[m];
                As[4*k4+0][m] = fmaxf(fmaf(av, g0, c0), 0.f);
                As[4*k4+1][m] = fmaxf(fmaf(av, g1, c1), 0.f);
                As[4*k4+2][m] = fmaxf(fmaf(av, g2, c2), 0.f);
                As[4*k4+3][m] = fmaxf(fmaf(av, g3, c3), 0.f);
            }
        } else {
#pragma unroll
            for (int i = 0; i < 4; i++) {
                int m = r0 + 32*i;
                As[4*k4+0][m] = pa[i].x;
                As[4*k4+1][m] = pa[i].y;
                As[4*k4+2][m] = pa[i].z;
                As[4*k4+3][m] = pa[i].w;
            }
        }
        if (ch + 1 < NC) { ldW(ch+1); ldA(ch+1); }   // prefetch next chunk during compute
        __syncthreads();
        // ---- 32-deep rank-1 updates, 8x8 per thread ----
#pragma unroll
        for (int k = 0; k < 32; k++) {
            float a[8], b[8];
#pragma unroll
            for (int r = 0; r < 8; r++) a[r] = As[k][ty + 16*r];
#pragma unroll
            for (int cc = 0; cc < 8; cc++) b[cc] = Ws[k][tx + 16*cc];
#pragma unroll
            for (int r = 0; r < 8; r++)
#pragma unroll
                for (int cc = 0; cc < 8; cc++) accv[r][cc] = fmaf(a[r], b[cc], accv[r][cc]);
        }
    }

    // ---- epilogue: gate math + c/h update. Local col tx+16*cc = 32*g + (tx+16*q), cc = 2g+q
    float bi[2], bf[2], bg[2], bo[2];
#pragma unroll
    for (int q = 0; q < 2; q++) {
        int u = u0 + tx + 16*q;
        bi[q] = b1[u]        + b2[u];
        bf[q] = b1[LH+u]     + b2[LH+u];
        bg[q] = b1[2*LH+u]   + b2[2*LH+u];
        bo[q] = b1[3*LH+u]   + b2[3*LH+u];
    }
#pragma unroll
    for (int r = 0; r < 8; r++) {
        int m = m0 + ty + 16*r;
        if (m >= M) continue;
#pragma unroll
        for (int q = 0; q < 2; q++) {
            int u = u0 + tx + 16*q;
            float gi = accv[r][0+q] + bi[q];
            float gf = accv[r][2+q] + bf[q];
            float gg = accv[r][4+q] + bg[q];
            float go = accv[r][6+q] + bo[q];
            float cn;
            if (HAS_H) {
                float co = c[(size_t)m*LH + u];
                cn = sigm_(gf)*co + sigm_(gi)*tanh_(gg);
            } else {
                cn = sigm_(gi)*tanh_(gg);         // c0 = 0: f-gate drops out
            }
            float hn = sigm_(go)*tanh_(cn);
            c[(size_t)m*LH + u]     = cn;
            h_out[(size_t)m*LH + u] = hn;
        }
    }
}

// ---------------- head: out = x_t + relu(h@pw1^T+pb1)@pw2^T + pb2 ----------------
__global__ void k_head(const float* __restrict__ h, const float* __restrict__ x,
                       const float* __restrict__ pw1, const float* __restrict__ pb1,
                       const float* __restrict__ pw2, const float* __restrict__ pb2,
                       float* __restrict__ out, int NN) {
    __shared__ float w1s[128][65];     // transposed [k][j]
    __shared__ float w2s[64], b1s[64];
    const int tid = threadIdx.x;
    for (int idx = tid; idx < 64*128; idx += 256) {
        int j = idx >> 7, k = idx & 127;
        w1s[k][j] = pw1[idx];
    }
    if (tid < 64) { w2s[tid] = pw2[tid]; b1s[tid] = pb1[tid]; }
    __syncthreads();

    int warp = tid >> 5, lane = tid & 31;
    int n = blockIdx.x*8 + warp;
    if (n >= NN) return;
    const float* hr = h + (size_t)n*LH;
    float s0 = b1s[lane], s1 = b1s[lane+32];
#pragma unroll 8
    for (int k = 0; k < 128; k++) {
        float hv = hr[k];
        s0 = fmaf(hv, w1s[k][lane],    s0);
        s1 = fmaf(hv, w1s[k][lane+32], s1);
    }
    float part = fmaxf(s0, 0.f)*w2s[lane] + fmaxf(s1, 0.f)*w2s[lane+32];
#pragma unroll
    for (int o = 16; o; o >>= 1) part += __shfl_xor_sync(0xffffffffu, part, o);
    if (lane == 0) out[n] = part + pb2[0] + x[n*T_STEPS + (T_STEPS-1)];
}

// ---------------- launcher ----------------
extern "C" void kernel_launch(void* const* d_in, const int* in_sizes, int n_in,
                              void* d_out, int out_size) {
    const float* x    = (const float*)d_in[0];
    const int*   ei   = (const int*)  d_in[1];
    const float* gw   = (const float*)d_in[2];
    const float* gb   = (const float*)d_in[3];
    const float* wih0 = (const float*)d_in[4];
    const float* whh0 = (const float*)d_in[5];
    const float* bih0 = (const float*)d_in[6];
    const float* bhh0 = (const float*)d_in[7];
    const float* wih1 = (const float*)d_in[8];
    const float* whh1 = (const float*)d_in[9];
    const float* bih1 = (const float*)d_in[10];
    const float* bhh1 = (const float*)d_in[11];
    const float* pw1  = (const float*)d_in[12];
    const float* pb1  = (const float*)d_in[13];
    const float* pw2  = (const float*)d_in[14];
    const float* pb2  = (const float*)d_in[15];
    float* out = (float*)d_out;

    const int NN = in_sizes[0] / T_STEPS;   // 16000
    const int E  = in_sizes[1] / 2;         // 256000
    const int* src = ei;
    const int* dst = ei + E;

    float *p_deg, *p_dinv, *p_acc, *p_a, *p_y0, *p_hA, *p_hB, *p_c;
    cudaGetSymbolAddress((void**)&p_deg,  d_deg);
    cudaGetSymbolAddress((void**)&p_dinv, d_dinv);
    cudaGetSymbolAddress((void**)&p_acc,  d_acc);
    cudaGetSymbolAddress((void**)&p_a,    d_a);
    cudaGetSymbolAddress((void**)&p_y0,   d_y0);
    cudaGetSymbolAddress((void**)&p_hA,   d_hA);
    cudaGetSymbolAddress((void**)&p_hB,   d_hB);
    cudaGetSymbolAddress((void**)&p_c,    d_c);

    // GCN scalar aggregation -> per-(t,node) scalar d_a
    k_deg_init    <<<(NN + 255)/256, 256>>>(p_deg, NN);
    k_deg_edges   <<<(E  + 255)/256, 256>>>(dst, p_deg, E);
    k_dinv_accinit<<<(NN + 255)/256, 256>>>(x, p_deg, p_dinv, p_acc, NN);
    k_scatter     <<<(E  + 255)/256, 256>>>(src, dst, x, p_dinv, p_acc, E);
    k_afin        <<<(NN*T_STEPS + 255)/256, 256>>>(p_acc, p_dinv, p_a, NN);

    dim3 gS((NN + 127)/128, 4);

    // Layer 0: ih = feat@Wih0^T built on the fly (K=64), recurrent K=128
    k_fused<2, true, false><<<gS, 256>>>(p_a, gw, gb, wih0, nullptr, nullptr,
                                         bih0, bhh0, p_c, p_y0, NN);
    for (int t = 1; t < T_STEPS; t++)
        k_fused<2, true, true><<<gS, 256>>>(p_a + (size_t)t*NN, gw, gb, wih0,
                                            p_y0 + (size_t)(t-1)*NN*LH, whh0,
                                            bih0, bhh0, p_c,
                                            p_y0 + (size_t)t*NN*LH, NN);

    // Layer 1: ih = y0[t]@Wih1^T folded in (K=128), recurrent K=128
    k_fused<4, false, false><<<gS, 256>>>(p_y0, nullptr, nullptr, wih1, nullptr, nullptr,
                                          bih1, bhh1, p_c, p_hA, NN);
    float* hin = p_hA; float* hout = p_hB;
    for (int t = 1; t < T_STEPS; t++) {
        k_fused<4, false, true><<<gS, 256>>>(p_y0 + (size_t)t*NN*LH, nullptr, nullptr, wih1,
                                             hin, whh1, bih1, bhh1, p_c, hout, NN);
        float* tmp = hin; hin = hout; hout = tmp;
    }

    // Head + residual
    k_head<<<(NN + 7)/8, 256>>>(hin, x, pw1, pb1, pw2, pb2, out, NN);
}